// round 1
// baseline (speedup 1.0000x reference)
#include <cuda_runtime.h>

// MultiHeadAttention: B=4, N=2048, EMB=256, HEADS=8, HD=32, fp32 in/out.
// Pipeline:
//   1) qkv_gemm_kernel : Q/K/V = x @ W{q,k,v}.T + b, written head-split [B*H, N, HD]
//   2) attn_kernel     : flash-attention online softmax, scale 1/sqrt(EMB),
//                        output written concat-head [B*N, EMB]
//   3) out_gemm_kernel : out = O @ Wo.T + bo  -> d_out [B*N, EMB]
// exp2 is a degree-6 FMA polynomial (MUFU would be the chip bottleneck at 134M exps).

#define EMB   256
#define HEADS 8
#define HD    32
#define BATCH 4
#define SEQ   2048
#define M_TOT (BATCH * SEQ)   // 8192

__device__ float g_Q[(size_t)BATCH * HEADS * SEQ * HD];
__device__ float g_K[(size_t)BATCH * HEADS * SEQ * HD];
__device__ float g_V[(size_t)BATCH * HEADS * SEQ * HD];
__device__ float g_O[(size_t)M_TOT * EMB];

// ---------------------------------------------------------------------------
// fast 2^x for x <= 0 (clamped). Degree-6 Taylor of 2^f on f in [0,1),
// rel err ~1e-5. Pure FMA/ALU pipe: no MUFU.
// ---------------------------------------------------------------------------
__device__ __forceinline__ float exp2s(float x) {
    x = fmaxf(x, -120.0f);
    float xf = floorf(x);
    float f  = x - xf;                       // [0,1)
    float p  = 1.5403530e-4f;
    p = fmaf(p, f, 1.3333558e-3f);
    p = fmaf(p, f, 9.6181291e-3f);
    p = fmaf(p, f, 5.5504109e-2f);
    p = fmaf(p, f, 2.4022651e-1f);
    p = fmaf(p, f, 6.9314718e-1f);
    p = fmaf(p, f, 1.0f);
    return p * __int_as_float(((int)xf + 127) << 23);
}

// ---------------------------------------------------------------------------
// Tiled NT GEMM: C[m,e] = sum_k A[m,k] * W[e,k] + bias[e]
// M x 256 @ (256 x 256)^T.  BM=BN=64, BK=32, 16x16 threads, 4x4 micro-tile.
// Smem tiles stored transposed [k][m] (stride 68) so operand reads are
// LDS.128 (a: broadcast, b: conflict-free contiguous).
// SPLIT=1 writes head-split layout [B*H, SEQ, HD]; SPLIT=0 plain [M, EMB].
// ---------------------------------------------------------------------------
template <int SPLIT>
__device__ __forceinline__ void gemm_body(const float* __restrict__ A,
                                          const float* __restrict__ W,
                                          const float* __restrict__ bias,
                                          float* __restrict__ C)
{
    __shared__ float As[32][68];   // [k][m]
    __shared__ float Ws[32][68];   // [k][e]

    const int t  = threadIdx.x;
    const int tx = t & 15;
    const int ty = t >> 4;
    const int m0 = blockIdx.x * 64;
    const int e0 = blockIdx.y * 64;

    // load mapping: thread t owns row (t/4) of the 64-row tile,
    // cols [(t%4)*8 .. +8) (two float4 global loads, 8 transposed smem stores)
    const int lm = t >> 2;
    const int lk = (t & 3) * 8;

    float acc[4][4] = {};

    for (int k0 = 0; k0 < EMB; k0 += 32) {
        float4 a0 = *(const float4*)(A + (size_t)(m0 + lm) * EMB + k0 + lk);
        float4 a1 = *(const float4*)(A + (size_t)(m0 + lm) * EMB + k0 + lk + 4);
        float4 w0 = *(const float4*)(W + (size_t)(e0 + lm) * EMB + k0 + lk);
        float4 w1 = *(const float4*)(W + (size_t)(e0 + lm) * EMB + k0 + lk + 4);
        As[lk + 0][lm] = a0.x; As[lk + 1][lm] = a0.y;
        As[lk + 2][lm] = a0.z; As[lk + 3][lm] = a0.w;
        As[lk + 4][lm] = a1.x; As[lk + 5][lm] = a1.y;
        As[lk + 6][lm] = a1.z; As[lk + 7][lm] = a1.w;
        Ws[lk + 0][lm] = w0.x; Ws[lk + 1][lm] = w0.y;
        Ws[lk + 2][lm] = w0.z; Ws[lk + 3][lm] = w0.w;
        Ws[lk + 4][lm] = w1.x; Ws[lk + 5][lm] = w1.y;
        Ws[lk + 6][lm] = w1.z; Ws[lk + 7][lm] = w1.w;
        __syncthreads();

        #pragma unroll
        for (int kk = 0; kk < 32; ++kk) {
            float4 av = *(const float4*)&As[kk][ty * 4];
            float4 bv = *(const float4*)&Ws[kk][tx * 4];
            float a[4] = {av.x, av.y, av.z, av.w};
            float b[4] = {bv.x, bv.y, bv.z, bv.w};
            #pragma unroll
            for (int i = 0; i < 4; ++i)
                #pragma unroll
                for (int j = 0; j < 4; ++j)
                    acc[i][j] = fmaf(a[i], b[j], acc[i][j]);
        }
        __syncthreads();
    }

    #pragma unroll
    for (int i = 0; i < 4; ++i) {
        const int m = m0 + ty * 4 + i;
        #pragma unroll
        for (int j = 0; j < 4; ++j) {
            const int e = e0 + tx * 4 + j;
            const float v = acc[i][j] + bias[e];
            if (SPLIT) {
                const int b_ = m >> 11, n_ = m & (SEQ - 1);
                const int h_ = e >> 5, d_ = e & (HD - 1);
                C[(((size_t)(b_ * HEADS + h_) * SEQ) + n_) * HD + d_] = v;
            } else {
                C[(size_t)m * EMB + e] = v;
            }
        }
    }
}

__global__ void __launch_bounds__(256)
qkv_gemm_kernel(const float* __restrict__ x,
                const float* __restrict__ Wq, const float* __restrict__ bq,
                const float* __restrict__ Wk, const float* __restrict__ bk,
                const float* __restrict__ Wv, const float* __restrict__ bv)
{
    const float* W; const float* b; float* dst;
    if (blockIdx.z == 0)      { W = Wq; b = bq; dst = g_Q; }
    else if (blockIdx.z == 1) { W = Wk; b = bk; dst = g_K; }
    else                      { W = Wv; b = bv; dst = g_V; }
    gemm_body<1>(x, W, b, dst);
}

__global__ void __launch_bounds__(256)
out_gemm_kernel(const float* __restrict__ Wo, const float* __restrict__ bo,
                float* __restrict__ out)
{
    gemm_body<0>(g_O, Wo, bo, out);
}

// ---------------------------------------------------------------------------
// Flash attention: one block = one (b,h) and 128 query rows; one thread = one
// query row (q, acc in registers). K/V tiles of 64 rows staged in smem.
// Scale 1/sqrt(EMB) and log2(e) folded into q so softmax runs in base-2.
// ---------------------------------------------------------------------------
__global__ void __launch_bounds__(128)
attn_kernel()
{
    const int bh = blockIdx.y;                       // 0..31
    const int qi = blockIdx.x * 128 + threadIdx.x;   // query row in [0,SEQ)

    const float* Qp    = g_Q + ((size_t)bh * SEQ + qi) * HD;
    const float* Kbase = g_K + (size_t)bh * SEQ * HD;
    const float* Vbase = g_V + (size_t)bh * SEQ * HD;

    __shared__ float4 Ks[512];   // 64 rows x 32 floats
    __shared__ float4 Vs[512];

    const float sc = 0.0625f * 1.4426950408889634f;  // 1/sqrt(256) * log2(e)
    float q[HD], acc[HD];
    #pragma unroll
    for (int c = 0; c < 8; ++c) {
        float4 v = ((const float4*)Qp)[c];
        q[4*c+0] = v.x * sc; q[4*c+1] = v.y * sc;
        q[4*c+2] = v.z * sc; q[4*c+3] = v.w * sc;
    }
    #pragma unroll
    for (int d = 0; d < HD; ++d) acc[d] = 0.0f;

    float mmax = -1e30f, l = 0.0f;

    for (int kt = 0; kt < SEQ; kt += 64) {
        __syncthreads();
        const float4* kg = (const float4*)(Kbase + (size_t)kt * HD);
        const float4* vg = (const float4*)(Vbase + (size_t)kt * HD);
        #pragma unroll
        for (int c = 0; c < 4; ++c) {
            Ks[threadIdx.x + 128 * c] = kg[threadIdx.x + 128 * c];
            Vs[threadIdx.x + 128 * c] = vg[threadIdx.x + 128 * c];
        }
        __syncthreads();

        #pragma unroll 2
        for (int j = 0; j < 64; ++j) {
            const float4* krow = Ks + j * 8;
            float s = 0.0f;
            #pragma unroll
            for (int c = 0; c < 8; ++c) {
                float4 kv = krow[c];
                s = fmaf(q[4*c+0], kv.x, s);
                s = fmaf(q[4*c+1], kv.y, s);
                s = fmaf(q[4*c+2], kv.z, s);
                s = fmaf(q[4*c+3], kv.w, s);
            }
            if (s > mmax) {                       // rare after warm-up
                float corr = exp2s(mmax - s);
                l *= corr;
                #pragma unroll
                for (int d = 0; d < HD; ++d) acc[d] *= corr;
                mmax = s;
            }
            float p = exp2s(s - mmax);
            l += p;
            const float4* vrow = Vs + j * 8;
            #pragma unroll
            for (int c = 0; c < 8; ++c) {
                float4 vv = vrow[c];
                acc[4*c+0] = fmaf(p, vv.x, acc[4*c+0]);
                acc[4*c+1] = fmaf(p, vv.y, acc[4*c+1]);
                acc[4*c+2] = fmaf(p, vv.z, acc[4*c+2]);
                acc[4*c+3] = fmaf(p, vv.w, acc[4*c+3]);
            }
        }
    }

    const float inv = 1.0f / l;
    const int b_ = bh >> 3, h_ = bh & 7;
    float* op = g_O + ((size_t)(b_ * SEQ + qi)) * EMB + h_ * HD;
    #pragma unroll
    for (int c = 0; c < 8; ++c) {
        float4 o;
        o.x = acc[4*c+0] * inv; o.y = acc[4*c+1] * inv;
        o.z = acc[4*c+2] * inv; o.w = acc[4*c+3] * inv;
        ((float4*)op)[c] = o;
    }
}

// ---------------------------------------------------------------------------
extern "C" void kernel_launch(void* const* d_in, const int* in_sizes, int n_in,
                              void* d_out, int out_size)
{
    const float* x  = (const float*)d_in[0];
    const float* Wq = (const float*)d_in[1];
    const float* bq = (const float*)d_in[2];
    const float* Wk = (const float*)d_in[3];
    const float* bk = (const float*)d_in[4];
    const float* Wv = (const float*)d_in[5];
    const float* bv = (const float*)d_in[6];
    const float* Wo = (const float*)d_in[7];
    const float* bo = (const float*)d_in[8];
    float* out = (float*)d_out;

    dim3 gqkv(M_TOT / 64, EMB / 64, 3);     // 128 x 4 x 3
    qkv_gemm_kernel<<<gqkv, 256>>>(x, Wq, bq, Wk, bk, Wv, bv);

    dim3 gattn(SEQ / 128, BATCH * HEADS);   // 16 x 32
    attn_kernel<<<gattn, 128>>>();

    dim3 gout(M_TOT / 64, EMB / 64);        // 128 x 4
    out_gemm_kernel<<<gout, 256>>>(Wo, bo, out);
}